// round 10
// baseline (speedup 1.0000x reference)
#include <cuda_runtime.h>
#include <cstdint>
#include <math.h>

#define L_TOT   12544
#define C_IN    64
#define C_OUT   64
#define K_TOT   576
#define M_TILE  128
#define KC      32
#define NCHUNK  (K_TOT / KC)   // 18
#define NTHREADS 512

#define PAD_W   114
#define PAD_S   (PAD_W * PAD_W)    // 12996 per (b,c) plane
#define NBATCH  8

// ---- smem byte offsets (single-buffer, ~58KB -> 2 CTAs/SM) ----
#define OFF_TMEM 0
#define OFF_MBAR 8
#define OFF_WSUM 64            // 64 floats
#define OFF_OFFT 320           // 576 ints
#define OFF_A1   3072          // [128][32] tf32, 16KB
#define OFF_A2   (OFF_A1 + 16384)
#define OFF_A3   (OFF_A2 + 16384)
#define OFF_B    (OFF_A3 + 16384)   // [64][32] tf32, 8KB
#define SMEM_TOTAL (OFF_B + 8192)   // 59392

// idesc: dtype=F32(1<<4), atype=TF32(2<<7), btype=TF32(2<<10), N=64(8<<17), M=128(8<<24)
#define IDESC_TF32 0x8100910u

#if defined(__CUDA_ARCH_FEAT_SM103_ALL) || \
    (defined(__CUDA_ARCH_SPECIFIC__) && (__CUDA_ARCH_SPECIFIC__ == 1030)) || \
    (defined(__CUDA_ARCH_FAMILY_SPECIFIC__) && (__CUDA_ARCH_FAMILY_SPECIFIC__ == 1030))
#define HAS_TCGEN05 1
#else
#define HAS_TCGEN05 0
#endif

// scratch: padded tf32-rounded u planes + tf32-rounded weights
__device__ float g_upad[NBATCH * C_IN * PAD_S];   // 26.6 MB
__device__ float g_wtf[C_OUT * K_TOT];
__device__ float g_wsum[C_OUT];

__device__ __forceinline__ float tf32r_(float x) {
    float y; asm("cvt.rna.tf32.f32 %0, %1;" : "=f"(y) : "f"(x)); return y;
}

// rowsum + tf32-rounded weight copy
__global__ void wprep_kernel(const float* __restrict__ w) {
    int o = threadIdx.x;
    if (o >= C_OUT) return;
    float s = 0.f;
    #pragma unroll 8
    for (int k = 0; k < K_TOT; ++k) {
        float v = w[o * K_TOT + k];
        s += v;
        g_wtf[o * K_TOT + k] = tf32r_(v);
    }
    g_wsum[o] = s;
}

// build zero-padded tf32-rounded u plane: g_upad[b,c,py,px]
__global__ void uprep_kernel(const float* __restrict__ img) {
    int p = blockIdx.x * blockDim.x + threadIdx.x;
    if (p >= PAD_S) return;
    int c = blockIdx.y, b = blockIdx.z;
    int py = p / PAD_W, px = p - py * PAD_W;
    float v = 0.f;
    if ((unsigned)(py - 1) < 112u && (unsigned)(px - 1) < 112u)
        v = tf32r_(img[((size_t)(b * C_IN + c)) * L_TOT + (py - 1) * 112 + (px - 1)]);
    g_upad[((size_t)(b * C_IN + c)) * PAD_S + p] = v;
}

__device__ __forceinline__ float sigm(float x) { return 1.f / (1.f + __expf(-x)); }

__device__ __forceinline__ float epilogue(float S, float c1, float c2, float c3) {
    const float Kf = (float)K_TOT;
    float f = (-0.000287f * S + 0.266f * c1 - 0.1097f * c2) * (1.f / 75.f);

    float g1 = (0.11f  / 75.f) * Kf + 0.001309f * S + 0.00619f  * c1 - 0.009f    * c2 + 0.001383f * c3;
    float g2 = (0.179f / 75.f) * Kf - 0.0025f   * S + 0.00303f  * c1 - 0.00484f  * c2 + 0.0175f   * c3;
    float g3 = (0.238f / 75.f) * Kf - 0.000954f * S + 0.00187f  * c1 + 0.001877f * c2 + 0.01502f  * c3;
    float g4 = (0.388f / 75.f) * Kf - 0.00734f  * S + 0.001117f * c1 + 0.00752f  * c2 + 0.009f    * c3;
    float g5 = (0.507f / 75.f) * Kf - 0.01017f  * S + 0.000426f * c1 + 0.00837f  * c2 + 0.00413f  * c3;

    float t1 = sigm(10.f * (0.15f - f));
    float t2 = sigm(10.f * (0.23f - f));
    float t3 = sigm(10.f * (0.32f - f));
    float t4 = sigm(10.f * (0.39f - f));

    return g5 + t1 * (g1 - g2) + t2 * (g2 - g3) + t3 * (g3 - g4) + t4 * (g4 - g5);
}

#if HAS_TCGEN05
// ---------------- PTX helpers (sm_103a only) ----------------
__device__ __forceinline__ uint32_t smem_u32(const void* p) {
    uint32_t a;
    asm("{ .reg .u64 t; cvta.to.shared.u64 t, %1; cvt.u32.u64 %0, t; }" : "=r"(a) : "l"(p));
    return a;
}
__device__ __forceinline__ uint32_t elect_one() {
    uint32_t p;
    asm volatile("{ .reg .pred p; elect.sync _|p, 0xFFFFFFFF; selp.b32 %0, 1, 0, p; }" : "=r"(p));
    return p;
}

#define MBARRIER_INIT(addr, cnt) \
    asm volatile("mbarrier.init.shared.b64 [%0], %1;" :: "r"((uint32_t)(addr)), "r"((uint32_t)(cnt)) : "memory")

#define MBARRIER_WAIT_PARITY(mb, par) do {                                          \
    uint32_t _mb = (uint32_t)(mb), _p = (uint32_t)(par), _d;                        \
    asm volatile("{ .reg .pred p; mbarrier.try_wait.parity.acquire.cta.shared::cta.b64 p, [%1], %2; selp.b32 %0,1,0,p; }" \
        : "=r"(_d) : "r"(_mb), "r"(_p) : "memory");                                 \
    if (!_d) {                                                                      \
        asm volatile("{ .reg .pred P1;\n\t"                                         \
            "WL_%=: mbarrier.try_wait.parity.acquire.cta.shared::cta.b64 P1, [%0], %1, 0x989680;\n\t" \
            "@P1 bra.uni WD_%=;\n\t bra.uni WL_%=;\n\t WD_%=: }"                    \
            :: "r"(_mb), "r"(_p) : "memory");                                       \
    }                                                                               \
} while (0)

#define TCGEN05_ALLOC(sm, n) \
    asm volatile("tcgen05.alloc.cta_group::1.sync.aligned.shared::cta.b32 [%0], %1;" \
        :: "r"((uint32_t)(sm)), "r"((uint32_t)(n)) : "memory")
#define TCGEN05_RELINQ() \
    asm volatile("tcgen05.relinquish_alloc_permit.cta_group::1.sync.aligned;")
#define TCGEN05_DEALLOC(t, n) \
    asm volatile("tcgen05.dealloc.cta_group::1.sync.aligned.b32 %0, %1;" :: "r"(t), "r"((uint32_t)(n)))
#define TCGEN05_COMMIT(mb) \
    asm volatile("tcgen05.commit.cta_group::1.mbarrier::arrive::one.shared::cluster.b64 [%0];" \
        :: "r"((uint32_t)(mb)) : "memory")
#define TCGEN05_WAIT_LD()  asm volatile("tcgen05.wait::ld.sync.aligned;" ::: "memory")
#define TCGEN05_FENCE_AFTER() asm volatile("tcgen05.fence::after_thread_sync;" ::: "memory")

#define TCGEN05_LD_X16(r, addr) \
    asm volatile("tcgen05.ld.sync.aligned.32x32b.x16.b32 " \
        "{%0,%1,%2,%3,%4,%5,%6,%7,%8,%9,%10,%11,%12,%13,%14,%15}, [%16];" \
        : "=r"((r)[0]),"=r"((r)[1]),"=r"((r)[2]),"=r"((r)[3]),   \
          "=r"((r)[4]),"=r"((r)[5]),"=r"((r)[6]),"=r"((r)[7]),   \
          "=r"((r)[8]),"=r"((r)[9]),"=r"((r)[10]),"=r"((r)[11]), \
          "=r"((r)[12]),"=r"((r)[13]),"=r"((r)[14]),"=r"((r)[15]) \
        : "r"(addr))

// SW128 K-major smem descriptor (layout=2, version=1, SBO=64, LBO=1)
__device__ __forceinline__ uint64_t make_desc_sw128(uint32_t addr) {
    return ((uint64_t)2 << 61) | ((uint64_t)1 << 46) | ((uint64_t)64 << 32) |
           ((uint64_t)1 << 16) | ((uint64_t)(addr >> 4) & 0x3FFF);
}

__device__ __forceinline__ void mma_tf32_ss(uint32_t d, uint64_t ad, uint64_t bd,
                                            uint32_t idesc, uint32_t en) {
    asm volatile(
        "{ .reg .pred p; setp.ne.u32 p, %4, 0;\n\t"
        "tcgen05.mma.cta_group::1.kind::tf32 [%0], %1, %2, %3, {%5,%5,%5,%5}, p; }\n"
        :: "r"(d), "l"(ad), "l"(bd), "r"(idesc), "r"(en), "r"(0u) : "memory");
}
#endif // HAS_TCGEN05

// ---------------- main kernel ----------------
__global__ __launch_bounds__(NTHREADS, 2) void conv_tc_kernel(
    const float* __restrict__ img,
    const float* __restrict__ wts,
    float* __restrict__ out)
{
#if HAS_TCGEN05
    extern __shared__ char smem[];
    const uint32_t sb = smem_u32(smem);
    const int tid = threadIdx.x, wid = tid >> 5, lane = tid & 31;
    const int bx = blockIdx.x;
    const int b = bx / 98, mb = bx - b * 98;
    const int m_base = mb * M_TILE;

    // TMEM alloc + mbar init + tables
    if (wid == 0) { TCGEN05_ALLOC(sb + OFF_TMEM, 256); TCGEN05_RELINQ(); }
    if (tid == 0) MBARRIER_INIT(sb + OFF_MBAR, 1);
    if (tid < C_OUT) ((float*)(smem + OFF_WSUM))[tid] = g_wsum[tid];
    for (int k = tid; k < K_TOT; k += NTHREADS) {
        int c = k / 9, t = k - c * 9, dy = t / 3, dx = t - dy * 3;
        ((int*)(smem + OFF_OFFT))[k] = c * PAD_S + dy * PAD_W + dx;   // element offset, no mask
    }
    __syncthreads();
    uint32_t tmem;
    asm volatile("ld.shared.b32 %0, [%1];" : "=r"(tmem) : "r"(sb + OFF_TMEM));

    // per-thread staging geometry (loop-invariant); padded plane => no masks
    const int m  = tid & 127;
    const int qg = tid >> 7;          // 0..3; this thread stages quads qg*2, qg*2+1
    const int gm = m_base + m;
    const int y  = gm / 112, x = gm - y * 112;
    const float* up = g_upad + (size_t)b * C_IN * PAD_S + (y * PAD_W + x);

    // hoisted swizzled A store offsets (2 quads per thread) + B offset (1 task)
    uint32_t swoff[2];
    #pragma unroll
    for (int i = 0; i < 2; ++i) {
        uint32_t bo = (uint32_t)(m * 128 + (qg * 2 + i) * 16);
        swoff[i] = bo ^ ((bo >> 3) & 0x70);
    }
    const int bo_o = tid >> 3, bo_q = tid & 7;
    uint32_t bsw;
    { uint32_t v = (uint32_t)(bo_o * 128 + bo_q * 16); bsw = v ^ ((v >> 3) & 0x70); }

    const uint64_t ad1 = make_desc_sw128(sb + OFF_A1);
    const uint64_t ad2 = make_desc_sw128(sb + OFF_A2);
    const uint64_t ad3 = make_desc_sw128(sb + OFF_A3);
    const uint64_t bd  = make_desc_sw128(sb + OFF_B);
    const int* offt = (const int*)(smem + OFF_OFFT);

    // ---- register prefetch buffers (8 u values + 1 pre-rounded B float4) ----
    float av[8];
    float4 bw;

    #define PREFETCH(K0) do {                                                   \
        bw = *(const float4*)(g_wtf + bo_o * K_TOT + (K0) + bo_q * 4);          \
        _Pragma("unroll")                                                       \
        for (int _i = 0; _i < 2; ++_i) {                                        \
            int4 pk = *(const int4*)(offt + (K0) + (qg * 2 + _i) * 4);          \
            av[_i * 4 + 0] = __ldg(up + pk.x);                                  \
            av[_i * 4 + 1] = __ldg(up + pk.y);                                  \
            av[_i * 4 + 2] = __ldg(up + pk.z);                                  \
            av[_i * 4 + 3] = __ldg(up + pk.w);                                  \
        }                                                                       \
    } while (0)

    PREFETCH(0);

    int ph = 0;
    for (int ch = 0; ch < NCHUNK; ++ch) {
        // wait until previous chunk's MMAs finished reading smem
        if (ch > 0) { MBARRIER_WAIT_PARITY(sb + OFF_MBAR, ph); ph ^= 1; }

        // ---- store registers -> smem (u already tf32-rounded; powers rounded here) ----
        *(float4*)(smem + OFF_B + bsw) = bw;
        #pragma unroll
        for (int i = 0; i < 2; ++i) {
            float4 r1, r2, r3;
            float* p1 = &r1.x; float* p2 = &r2.x; float* p3 = &r3.x;
            #pragma unroll
            for (int j = 0; j < 4; ++j) {
                float v = av[i * 4 + j];
                float v2 = v * v;
                p1[j] = v;
                p2[j] = tf32r_(v2);
                p3[j] = tf32r_(v2 * v);
            }
            *(float4*)(smem + OFF_A1 + swoff[i]) = r1;
            *(float4*)(smem + OFF_A2 + swoff[i]) = r2;
            *(float4*)(smem + OFF_A3 + swoff[i]) = r3;
        }
        asm volatile("fence.proxy.async.shared::cta;" ::: "memory");
        __syncthreads();

        // ---- issue MMAs for this chunk ----
        if (wid == 0 && elect_one()) {
            #pragma unroll
            for (int st = 0; st < 4; ++st) {
                uint32_t en = (ch > 0 || st > 0) ? 1u : 0u;
                mma_tf32_ss(tmem + 0,   ad1 + st * 2, bd + st * 2, IDESC_TF32, en);
                mma_tf32_ss(tmem + 64,  ad2 + st * 2, bd + st * 2, IDESC_TF32, en);
                mma_tf32_ss(tmem + 128, ad3 + st * 2, bd + st * 2, IDESC_TF32, en);
            }
            TCGEN05_COMMIT(sb + OFF_MBAR);
        }

        // ---- prefetch next chunk (overlaps the MMAs just issued) ----
        if (ch + 1 < NCHUNK) PREFETCH((ch + 1) * KC);
    }
    // drain last chunk
    MBARRIER_WAIT_PARITY(sb + OFF_MBAR, ph);

    // ---- fused epilogue from TMEM (16 warps: warp -> (m-subpartition, 16-col group)) ----
    TCGEN05_FENCE_AFTER();
    const int msub = wid & 3;
    const int n0   = (wid >> 2) * 16;
    const float* sw = (const float*)(smem + OFF_WSUM);
    const int mg = m_base + msub * 32 + lane;

    {
        uint32_t a1[16], a2[16], a3[16];
        TCGEN05_LD_X16(a1, tmem + 0   + n0);
        TCGEN05_LD_X16(a2, tmem + 64  + n0);
        TCGEN05_LD_X16(a3, tmem + 128 + n0);
        TCGEN05_WAIT_LD();
        #pragma unroll
        for (int ni = 0; ni < 16; ++ni) {
            const int o = n0 + ni;
            float res = epilogue(sw[o],
                                 __uint_as_float(a1[ni]),
                                 __uint_as_float(a2[ni]),
                                 __uint_as_float(a3[ni]));
            out[(size_t)(b * C_OUT + o) * L_TOT + mg] = res;
        }
    }

    __syncthreads();
    if (wid == 0) TCGEN05_DEALLOC(tmem, 256);
#else
    // ---------- fallback for non-sm_103a compilation passes (never runs on GB300) ----------
    const int tid = threadIdx.x;
    const int bx = blockIdx.x;
    const int b = bx / 98, mb = bx - b * 98;
    const int m_base = mb * M_TILE;
    const float* imgb = img + (size_t)b * C_IN * L_TOT;

    for (int idx = tid; idx < M_TILE * C_OUT; idx += NTHREADS) {
        int m = idx & 127, o = idx >> 7;
        int gm = m_base + m;
        int y = gm / 112, x = gm - y * 112;
        float c1 = 0.f, c2 = 0.f, c3 = 0.f;
        for (int k = 0; k < K_TOT; ++k) {
            int c = k / 9, r = k - c * 9, dy = r / 3, dx = r - dy * 3;
            int iy = y + dy - 1, ix = x + dx - 1;
            float v = 0.f;
            if ((unsigned)iy < 112u && (unsigned)ix < 112u)
                v = imgb[c * L_TOT + iy * 112 + ix];
            float w = wts[o * K_TOT + k];
            c1 += v * w; c2 += v * v * w; c3 += v * v * v * w;
        }
        out[(size_t)(b * C_OUT + o) * L_TOT + gm] = epilogue(g_wsum[o], c1, c2, c3);
    }
#endif
}

extern "C" void kernel_launch(void* const* d_in, const int* in_sizes, int n_in,
                              void* d_out, int out_size) {
    const float* img = (const float*)d_in[0];
    const float* wts = (const float*)d_in[1];
    float* out = (float*)d_out;

    int B = in_sizes[0] / (C_IN * L_TOT);   // 8

    cudaFuncSetAttribute(conv_tc_kernel, cudaFuncAttributeMaxDynamicSharedMemorySize, SMEM_TOTAL);

    wprep_kernel<<<1, 64>>>(wts);
    {
        dim3 pg((PAD_S + 511) / 512, C_IN, B);
        uprep_kernel<<<pg, 512>>>(img);
    }
    conv_tc_kernel<<<B * 98, NTHREADS, SMEM_TOTAL>>>(img, wts, out);
}

// round 11
// speedup vs baseline: 1.4154x; 1.4154x over previous
#include <cuda_runtime.h>
#include <cstdint>
#include <math.h>

#define L_TOT   12544
#define C_IN    64
#define C_OUT   64
#define K_TOT   576
#define M_TILE  128
#define KC      32
#define NCHUNK  (K_TOT / KC)   // 18
#define NTHREADS 512

#define PAD_W   114
#define PAD_S   (PAD_W * PAD_W)    // 12996 per (b,c) plane
#define NBATCH  8

// ---- smem byte offsets (single-buffer, ~58KB -> 2 CTAs/SM) ----
#define OFF_TMEM 0
#define OFF_MBAR 8
#define OFF_WSUM 64            // 64 floats
#define OFF_OFFT 320           // 576 ints
#define OFF_A1   3072          // [128][32] tf32, 16KB
#define OFF_A2   (OFF_A1 + 16384)
#define OFF_A3   (OFF_A2 + 16384)
#define OFF_B    (OFF_A3 + 16384)   // [64][32] tf32, 8KB
#define SMEM_TOTAL (OFF_B + 8192)   // 59392

// idesc: dtype=F32(1<<4), atype=TF32(2<<7), btype=TF32(2<<10), N=64(8<<17), M=128(8<<24)
#define IDESC_TF32 0x8100910u

#if defined(__CUDA_ARCH_FEAT_SM103_ALL) || \
    (defined(__CUDA_ARCH_SPECIFIC__) && (__CUDA_ARCH_SPECIFIC__ == 1030)) || \
    (defined(__CUDA_ARCH_FAMILY_SPECIFIC__) && (__CUDA_ARCH_FAMILY_SPECIFIC__ == 1030))
#define HAS_TCGEN05 1
#else
#define HAS_TCGEN05 0
#endif

// scratch: padded tf32-rounded u planes + tf32-rounded weights
__device__ float g_upad[NBATCH * C_IN * PAD_S];   // 26.6 MB
__device__ float g_wtf[C_OUT * K_TOT];
__device__ float g_wsum[C_OUT];

__device__ __forceinline__ float tf32r_(float x) {
    float y; asm("cvt.rna.tf32.f32 %0, %1;" : "=f"(y) : "f"(x)); return y;
}

// rowsum + tf32-rounded weight copy: one warp per output channel
__global__ void wprep_kernel(const float* __restrict__ w) {
    int o    = blockIdx.x * (blockDim.x >> 5) + (threadIdx.x >> 5);
    int lane = threadIdx.x & 31;
    if (o >= C_OUT) return;
    float s = 0.f;
    #pragma unroll
    for (int k = lane; k < K_TOT; k += 32) {
        float v = w[o * K_TOT + k];
        s += v;
        g_wtf[o * K_TOT + k] = tf32r_(v);
    }
    #pragma unroll
    for (int d = 16; d > 0; d >>= 1)
        s += __shfl_xor_sync(0xFFFFFFFFu, s, d);
    if (lane == 0) g_wsum[o] = s;
}

// build zero-padded tf32-rounded u plane: g_upad[b,c,py,px]
__global__ void uprep_kernel(const float* __restrict__ img) {
    int p = blockIdx.x * blockDim.x + threadIdx.x;
    if (p >= PAD_S) return;
    int c = blockIdx.y, b = blockIdx.z;
    int py = p / PAD_W, px = p - py * PAD_W;
    float v = 0.f;
    if ((unsigned)(py - 1) < 112u && (unsigned)(px - 1) < 112u)
        v = tf32r_(img[((size_t)(b * C_IN + c)) * L_TOT + (py - 1) * 112 + (px - 1)]);
    g_upad[((size_t)(b * C_IN + c)) * PAD_S + p] = v;
}

__device__ __forceinline__ float sigm(float x) { return 1.f / (1.f + __expf(-x)); }

__device__ __forceinline__ float epilogue(float S, float c1, float c2, float c3) {
    const float Kf = (float)K_TOT;
    float f = (-0.000287f * S + 0.266f * c1 - 0.1097f * c2) * (1.f / 75.f);

    float g1 = (0.11f  / 75.f) * Kf + 0.001309f * S + 0.00619f  * c1 - 0.009f    * c2 + 0.001383f * c3;
    float g2 = (0.179f / 75.f) * Kf - 0.0025f   * S + 0.00303f  * c1 - 0.00484f  * c2 + 0.0175f   * c3;
    float g3 = (0.238f / 75.f) * Kf - 0.000954f * S + 0.00187f  * c1 + 0.001877f * c2 + 0.01502f  * c3;
    float g4 = (0.388f / 75.f) * Kf - 0.00734f  * S + 0.001117f * c1 + 0.00752f  * c2 + 0.009f    * c3;
    float g5 = (0.507f / 75.f) * Kf - 0.01017f  * S + 0.000426f * c1 + 0.00837f  * c2 + 0.00413f  * c3;

    float t1 = sigm(10.f * (0.15f - f));
    float t2 = sigm(10.f * (0.23f - f));
    float t3 = sigm(10.f * (0.32f - f));
    float t4 = sigm(10.f * (0.39f - f));

    return g5 + t1 * (g1 - g2) + t2 * (g2 - g3) + t3 * (g3 - g4) + t4 * (g4 - g5);
}

#if HAS_TCGEN05
// ---------------- PTX helpers (sm_103a only) ----------------
__device__ __forceinline__ uint32_t smem_u32(const void* p) {
    uint32_t a;
    asm("{ .reg .u64 t; cvta.to.shared.u64 t, %1; cvt.u32.u64 %0, t; }" : "=r"(a) : "l"(p));
    return a;
}
__device__ __forceinline__ uint32_t elect_one() {
    uint32_t p;
    asm volatile("{ .reg .pred p; elect.sync _|p, 0xFFFFFFFF; selp.b32 %0, 1, 0, p; }" : "=r"(p));
    return p;
}

#define MBARRIER_INIT(addr, cnt) \
    asm volatile("mbarrier.init.shared.b64 [%0], %1;" :: "r"((uint32_t)(addr)), "r"((uint32_t)(cnt)) : "memory")

#define MBARRIER_WAIT_PARITY(mb, par) do {                                          \
    uint32_t _mb = (uint32_t)(mb), _p = (uint32_t)(par), _d;                        \
    asm volatile("{ .reg .pred p; mbarrier.try_wait.parity.acquire.cta.shared::cta.b64 p, [%1], %2; selp.b32 %0,1,0,p; }" \
        : "=r"(_d) : "r"(_mb), "r"(_p) : "memory");                                 \
    if (!_d) {                                                                      \
        asm volatile("{ .reg .pred P1;\n\t"                                         \
            "WL_%=: mbarrier.try_wait.parity.acquire.cta.shared::cta.b64 P1, [%0], %1, 0x989680;\n\t" \
            "@P1 bra.uni WD_%=;\n\t bra.uni WL_%=;\n\t WD_%=: }"                    \
            :: "r"(_mb), "r"(_p) : "memory");                                       \
    }                                                                               \
} while (0)

#define TCGEN05_ALLOC(sm, n) \
    asm volatile("tcgen05.alloc.cta_group::1.sync.aligned.shared::cta.b32 [%0], %1;" \
        :: "r"((uint32_t)(sm)), "r"((uint32_t)(n)) : "memory")
#define TCGEN05_RELINQ() \
    asm volatile("tcgen05.relinquish_alloc_permit.cta_group::1.sync.aligned;")
#define TCGEN05_DEALLOC(t, n) \
    asm volatile("tcgen05.dealloc.cta_group::1.sync.aligned.b32 %0, %1;" :: "r"(t), "r"((uint32_t)(n)))
#define TCGEN05_COMMIT(mb) \
    asm volatile("tcgen05.commit.cta_group::1.mbarrier::arrive::one.shared::cluster.b64 [%0];" \
        :: "r"((uint32_t)(mb)) : "memory")
#define TCGEN05_WAIT_LD()  asm volatile("tcgen05.wait::ld.sync.aligned;" ::: "memory")
#define TCGEN05_FENCE_AFTER() asm volatile("tcgen05.fence::after_thread_sync;" ::: "memory")

#define TCGEN05_LD_X16(r, addr) \
    asm volatile("tcgen05.ld.sync.aligned.32x32b.x16.b32 " \
        "{%0,%1,%2,%3,%4,%5,%6,%7,%8,%9,%10,%11,%12,%13,%14,%15}, [%16];" \
        : "=r"((r)[0]),"=r"((r)[1]),"=r"((r)[2]),"=r"((r)[3]),   \
          "=r"((r)[4]),"=r"((r)[5]),"=r"((r)[6]),"=r"((r)[7]),   \
          "=r"((r)[8]),"=r"((r)[9]),"=r"((r)[10]),"=r"((r)[11]), \
          "=r"((r)[12]),"=r"((r)[13]),"=r"((r)[14]),"=r"((r)[15]) \
        : "r"(addr))

// SW128 K-major smem descriptor (layout=2, version=1, SBO=64, LBO=1)
__device__ __forceinline__ uint64_t make_desc_sw128(uint32_t addr) {
    return ((uint64_t)2 << 61) | ((uint64_t)1 << 46) | ((uint64_t)64 << 32) |
           ((uint64_t)1 << 16) | ((uint64_t)(addr >> 4) & 0x3FFF);
}

__device__ __forceinline__ void mma_tf32_ss(uint32_t d, uint64_t ad, uint64_t bd,
                                            uint32_t idesc, uint32_t en) {
    asm volatile(
        "{ .reg .pred p; setp.ne.u32 p, %4, 0;\n\t"
        "tcgen05.mma.cta_group::1.kind::tf32 [%0], %1, %2, %3, {%5,%5,%5,%5}, p; }\n"
        :: "r"(d), "l"(ad), "l"(bd), "r"(idesc), "r"(en), "r"(0u) : "memory");
}
#endif // HAS_TCGEN05

// ---------------- main kernel ----------------
__global__ __launch_bounds__(NTHREADS, 2) void conv_tc_kernel(
    const float* __restrict__ img,
    const float* __restrict__ wts,
    float* __restrict__ out)
{
#if HAS_TCGEN05
    extern __shared__ char smem[];
    const uint32_t sb = smem_u32(smem);
    const int tid = threadIdx.x, wid = tid >> 5, lane = tid & 31;
    const int bx = blockIdx.x;
    const int b = bx / 98, mb = bx - b * 98;
    const int m_base = mb * M_TILE;

    // TMEM alloc + mbar init + tables
    if (wid == 0) { TCGEN05_ALLOC(sb + OFF_TMEM, 256); TCGEN05_RELINQ(); }
    if (tid == 0) MBARRIER_INIT(sb + OFF_MBAR, 1);
    if (tid < C_OUT) ((float*)(smem + OFF_WSUM))[tid] = g_wsum[tid];
    for (int k = tid; k < K_TOT; k += NTHREADS) {
        int c = k / 9, t = k - c * 9, dy = t / 3, dx = t - dy * 3;
        ((int*)(smem + OFF_OFFT))[k] = c * PAD_S + dy * PAD_W + dx;   // element offset, no mask
    }
    __syncthreads();
    uint32_t tmem;
    asm volatile("ld.shared.b32 %0, [%1];" : "=r"(tmem) : "r"(sb + OFF_TMEM));

    // per-thread staging geometry (loop-invariant); padded plane => no masks
    const int m  = tid & 127;
    const int qg = tid >> 7;          // 0..3; this thread stages quads qg*2, qg*2+1
    const int gm = m_base + m;
    const int y  = gm / 112, x = gm - y * 112;
    const float* up = g_upad + (size_t)b * C_IN * PAD_S + (y * PAD_W + x);

    // hoisted swizzled A store offsets (2 quads per thread) + B offset (1 task)
    uint32_t swoff[2];
    #pragma unroll
    for (int i = 0; i < 2; ++i) {
        uint32_t bo = (uint32_t)(m * 128 + (qg * 2 + i) * 16);
        swoff[i] = bo ^ ((bo >> 3) & 0x70);
    }
    const int bo_o = tid >> 3, bo_q = tid & 7;
    uint32_t bsw;
    { uint32_t v = (uint32_t)(bo_o * 128 + bo_q * 16); bsw = v ^ ((v >> 3) & 0x70); }

    const uint64_t ad1 = make_desc_sw128(sb + OFF_A1);
    const uint64_t ad2 = make_desc_sw128(sb + OFF_A2);
    const uint64_t ad3 = make_desc_sw128(sb + OFF_A3);
    const uint64_t bd  = make_desc_sw128(sb + OFF_B);
    const int* offt = (const int*)(smem + OFF_OFFT);

    // ---- register prefetch buffers (8 u values + 1 pre-rounded B float4) ----
    float av[8];
    float4 bw;

    #define PREFETCH(K0) do {                                                   \
        bw = *(const float4*)(g_wtf + bo_o * K_TOT + (K0) + bo_q * 4);          \
        _Pragma("unroll")                                                       \
        for (int _i = 0; _i < 2; ++_i) {                                        \
            int4 pk = *(const int4*)(offt + (K0) + (qg * 2 + _i) * 4);          \
            av[_i * 4 + 0] = __ldg(up + pk.x);                                  \
            av[_i * 4 + 1] = __ldg(up + pk.y);                                  \
            av[_i * 4 + 2] = __ldg(up + pk.z);                                  \
            av[_i * 4 + 3] = __ldg(up + pk.w);                                  \
        }                                                                       \
    } while (0)

    PREFETCH(0);

    int ph = 0;
    for (int ch = 0; ch < NCHUNK; ++ch) {
        // wait until previous chunk's MMAs finished reading smem
        if (ch > 0) { MBARRIER_WAIT_PARITY(sb + OFF_MBAR, ph); ph ^= 1; }

        // ---- store registers -> smem (u already tf32-rounded; powers rounded here) ----
        *(float4*)(smem + OFF_B + bsw) = bw;
        #pragma unroll
        for (int i = 0; i < 2; ++i) {
            float4 r1, r2, r3;
            float* p1 = &r1.x; float* p2 = &r2.x; float* p3 = &r3.x;
            #pragma unroll
            for (int j = 0; j < 4; ++j) {
                float v = av[i * 4 + j];
                float v2 = v * v;
                p1[j] = v;
                p2[j] = tf32r_(v2);
                p3[j] = tf32r_(v2 * v);
            }
            *(float4*)(smem + OFF_A1 + swoff[i]) = r1;
            *(float4*)(smem + OFF_A2 + swoff[i]) = r2;
            *(float4*)(smem + OFF_A3 + swoff[i]) = r3;
        }
        asm volatile("fence.proxy.async.shared::cta;" ::: "memory");
        __syncthreads();

        // ---- issue MMAs for this chunk ----
        if (wid == 0 && elect_one()) {
            #pragma unroll
            for (int st = 0; st < 4; ++st) {
                uint32_t en = (ch > 0 || st > 0) ? 1u : 0u;
                mma_tf32_ss(tmem + 0,   ad1 + st * 2, bd + st * 2, IDESC_TF32, en);
                mma_tf32_ss(tmem + 64,  ad2 + st * 2, bd + st * 2, IDESC_TF32, en);
                mma_tf32_ss(tmem + 128, ad3 + st * 2, bd + st * 2, IDESC_TF32, en);
            }
            TCGEN05_COMMIT(sb + OFF_MBAR);
        }

        // ---- prefetch next chunk (overlaps the MMAs just issued) ----
        if (ch + 1 < NCHUNK) PREFETCH((ch + 1) * KC);
    }
    // drain last chunk
    MBARRIER_WAIT_PARITY(sb + OFF_MBAR, ph);

    // ---- fused epilogue from TMEM (16 warps: warp -> (m-subpartition, 16-col group)) ----
    TCGEN05_FENCE_AFTER();
    const int msub = wid & 3;
    const int n0   = (wid >> 2) * 16;
    const float* sw = (const float*)(smem + OFF_WSUM);
    const int mg = m_base + msub * 32 + lane;

    {
        uint32_t a1[16], a2[16], a3[16];
        TCGEN05_LD_X16(a1, tmem + 0   + n0);
        TCGEN05_LD_X16(a2, tmem + 64  + n0);
        TCGEN05_LD_X16(a3, tmem + 128 + n0);
        TCGEN05_WAIT_LD();
        #pragma unroll
        for (int ni = 0; ni < 16; ++ni) {
            const int o = n0 + ni;
            float res = epilogue(sw[o],
                                 __uint_as_float(a1[ni]),
                                 __uint_as_float(a2[ni]),
                                 __uint_as_float(a3[ni]));
            out[(size_t)(b * C_OUT + o) * L_TOT + mg] = res;
        }
    }

    __syncthreads();
    if (wid == 0) TCGEN05_DEALLOC(tmem, 256);
#else
    // ---------- fallback for non-sm_103a compilation passes (never runs on GB300) ----------
    const int tid = threadIdx.x;
    const int bx = blockIdx.x;
    const int b = bx / 98, mb = bx - b * 98;
    const int m_base = mb * M_TILE;
    const float* imgb = img + (size_t)b * C_IN * L_TOT;

    for (int idx = tid; idx < M_TILE * C_OUT; idx += NTHREADS) {
        int m = idx & 127, o = idx >> 7;
        int gm = m_base + m;
        int y = gm / 112, x = gm - y * 112;
        float c1 = 0.f, c2 = 0.f, c3 = 0.f;
        for (int k = 0; k < K_TOT; ++k) {
            int c = k / 9, r = k - c * 9, dy = r / 3, dx = r - dy * 3;
            int iy = y + dy - 1, ix = x + dx - 1;
            float v = 0.f;
            if ((unsigned)iy < 112u && (unsigned)ix < 112u)
                v = imgb[c * L_TOT + iy * 112 + ix];
            float w = wts[o * K_TOT + k];
            c1 += v * w; c2 += v * v * w; c3 += v * v * v * w;
        }
        out[(size_t)(b * C_OUT + o) * L_TOT + gm] = epilogue(g_wsum[o], c1, c2, c3);
    }
#endif
}

extern "C" void kernel_launch(void* const* d_in, const int* in_sizes, int n_in,
                              void* d_out, int out_size) {
    const float* img = (const float*)d_in[0];
    const float* wts = (const float*)d_in[1];
    float* out = (float*)d_out;

    int B = in_sizes[0] / (C_IN * L_TOT);   // 8

    cudaFuncSetAttribute(conv_tc_kernel, cudaFuncAttributeMaxDynamicSharedMemorySize, SMEM_TOTAL);

    wprep_kernel<<<4, 512>>>(wts);   // 64 warps: one per output channel
    {
        dim3 pg((PAD_S + 511) / 512, C_IN, B);
        uprep_kernel<<<pg, 512>>>(img);
    }
    conv_tc_kernel<<<B * 98, NTHREADS, SMEM_TOTAL>>>(img, wts, out);
}

// round 14
// speedup vs baseline: 1.4175x; 1.0015x over previous
#include <cuda_runtime.h>
#include <cstdint>
#include <math.h>

#define L_TOT   12544
#define C_IN    64
#define C_OUT   64
#define K_TOT   576
#define M_TILE  128
#define KC      32
#define NCHUNK  (K_TOT / KC)   // 18
#define NTHREADS 512

#define PAD_W   114
#define PAD_S   (PAD_W * PAD_W)    // 12996 per (b,c) plane
#define NBATCH  8

// ---- smem layout: header + double-buffered A (2x48KB) + double-buffered B (2x8KB) ----
#define OFF_TMEM  0
#define OFF_MBAR0 8
#define OFF_MBAR1 16
#define OFF_A     1024
#define A_SSTRIDE 49152            // one stage: A1,A2,A3 (3 x 16KB)
#define A_PSTRIDE 16384
#define OFF_B     (OFF_A + 2 * A_SSTRIDE)   // 99328 (1024-aligned)
#define B_SSTRIDE 8192
#define SMEM_TOTAL (OFF_B + 2 * B_SSTRIDE)  // 115712 -> 2 CTAs/SM (231424 <= 233472)

// idesc: dtype=F32(1<<4), atype=TF32(2<<7), btype=TF32(2<<10), N=64(8<<17), M=128(8<<24)
#define IDESC_TF32 0x8100910u

#if defined(__CUDA_ARCH_FEAT_SM103_ALL) || \
    (defined(__CUDA_ARCH_SPECIFIC__) && (__CUDA_ARCH_SPECIFIC__ == 1030)) || \
    (defined(__CUDA_ARCH_FAMILY_SPECIFIC__) && (__CUDA_ARCH_FAMILY_SPECIFIC__ == 1030))
#define HAS_TCGEN05 1
#else
#define HAS_TCGEN05 0
#endif

// scratch: padded tf32-rounded u planes + tf32-rounded weights + tables
__device__ float g_upad[NBATCH * C_IN * PAD_S];   // 26.6 MB
__device__ float g_wtf[C_OUT * K_TOT];
__device__ float g_wsum[C_OUT];
__device__ int   g_offt[K_TOT];

__device__ __forceinline__ float tf32r_(float x) {
    float y; asm("cvt.rna.tf32.f32 %0, %1;" : "=f"(y) : "f"(x)); return y;
}

// rowsum + tf32-rounded weight copy: one warp per output channel; also fills g_offt
__global__ void wprep_kernel(const float* __restrict__ w) {
    int gt = blockIdx.x * blockDim.x + threadIdx.x;
    if (gt < K_TOT) {
        int c = gt / 9, t = gt - c * 9, dy = t / 3, dx = t - dy * 3;
        g_offt[gt] = c * PAD_S + dy * PAD_W + dx;
    }
    int o    = blockIdx.x * (blockDim.x >> 5) + (threadIdx.x >> 5);
    int lane = threadIdx.x & 31;
    if (o >= C_OUT) return;
    float s = 0.f;
    #pragma unroll
    for (int k = lane; k < K_TOT; k += 32) {
        float v = w[o * K_TOT + k];
        s += v;
        g_wtf[o * K_TOT + k] = tf32r_(v);
    }
    #pragma unroll
    for (int d = 16; d > 0; d >>= 1)
        s += __shfl_xor_sync(0xFFFFFFFFu, s, d);
    if (lane == 0) g_wsum[o] = s;
}

// build zero-padded tf32-rounded u plane: g_upad[b,c,py,px]
__global__ void uprep_kernel(const float* __restrict__ img) {
    int p = blockIdx.x * blockDim.x + threadIdx.x;
    if (p >= PAD_S) return;
    int c = blockIdx.y, b = blockIdx.z;
    int py = p / PAD_W, px = p - py * PAD_W;
    float v = 0.f;
    if ((unsigned)(py - 1) < 112u && (unsigned)(px - 1) < 112u)
        v = tf32r_(img[((size_t)(b * C_IN + c)) * L_TOT + (py - 1) * 112 + (px - 1)]);
    g_upad[((size_t)(b * C_IN + c)) * PAD_S + p] = v;
}

__device__ __forceinline__ float sigm(float x) { return 1.f / (1.f + __expf(-x)); }

__device__ __forceinline__ float epilogue(float S, float c1, float c2, float c3) {
    const float Kf = (float)K_TOT;
    float f = (-0.000287f * S + 0.266f * c1 - 0.1097f * c2) * (1.f / 75.f);

    float g1 = (0.11f  / 75.f) * Kf + 0.001309f * S + 0.00619f  * c1 - 0.009f    * c2 + 0.001383f * c3;
    float g2 = (0.179f / 75.f) * Kf - 0.0025f   * S + 0.00303f  * c1 - 0.00484f  * c2 + 0.0175f   * c3;
    float g3 = (0.238f / 75.f) * Kf - 0.000954f * S + 0.00187f  * c1 + 0.001877f * c2 + 0.01502f  * c3;
    float g4 = (0.388f / 75.f) * Kf - 0.00734f  * S + 0.001117f * c1 + 0.00752f  * c2 + 0.009f    * c3;
    float g5 = (0.507f / 75.f) * Kf - 0.01017f  * S + 0.000426f * c1 + 0.00837f  * c2 + 0.00413f  * c3;

    float t1 = sigm(10.f * (0.15f - f));
    float t2 = sigm(10.f * (0.23f - f));
    float t3 = sigm(10.f * (0.32f - f));
    float t4 = sigm(10.f * (0.39f - f));

    return g5 + t1 * (g1 - g2) + t2 * (g2 - g3) + t3 * (g3 - g4) + t4 * (g4 - g5);
}

#if HAS_TCGEN05
// ---------------- PTX helpers (sm_103a only) ----------------
__device__ __forceinline__ uint32_t smem_u32(const void* p) {
    uint32_t a;
    asm("{ .reg .u64 t; cvta.to.shared.u64 t, %1; cvt.u32.u64 %0, t; }" : "=r"(a) : "l"(p));
    return a;
}
__device__ __forceinline__ uint32_t elect_one() {
    uint32_t p;
    asm volatile("{ .reg .pred p; elect.sync _|p, 0xFFFFFFFF; selp.b32 %0, 1, 0, p; }" : "=r"(p));
    return p;
}

#define MBARRIER_INIT(addr, cnt) \
    asm volatile("mbarrier.init.shared.b64 [%0], %1;" :: "r"((uint32_t)(addr)), "r"((uint32_t)(cnt)) : "memory")

#define MBARRIER_WAIT_PARITY(mb, par) do {                                          \
    uint32_t _mb = (uint32_t)(mb), _p = (uint32_t)(par), _d;                        \
    asm volatile("{ .reg .pred p; mbarrier.try_wait.parity.acquire.cta.shared::cta.b64 p, [%1], %2; selp.b32 %0,1,0,p; }" \
        : "=r"(_d) : "r"(_mb), "r"(_p) : "memory");                                 \
    if (!_d) {                                                                      \
        asm volatile("{ .reg .pred P1;\n\t"                                         \
            "WL_%=: mbarrier.try_wait.parity.acquire.cta.shared::cta.b64 P1, [%0], %1, 0x989680;\n\t" \
            "@P1 bra.uni WD_%=;\n\t bra.uni WL_%=;\n\t WD_%=: }"                    \
            :: "r"(_mb), "r"(_p) : "memory");                                       \
    }                                                                               \
} while (0)

#define TCGEN05_ALLOC(sm, n) \
    asm volatile("tcgen05.alloc.cta_group::1.sync.aligned.shared::cta.b32 [%0], %1;" \
        :: "r"((uint32_t)(sm)), "r"((uint32_t)(n)) : "memory")
#define TCGEN05_RELINQ() \
    asm volatile("tcgen05.relinquish_alloc_permit.cta_group::1.sync.aligned;")
#define TCGEN05_DEALLOC(t, n) \
    asm volatile("tcgen05.dealloc.cta_group::1.sync.aligned.b32 %0, %1;" :: "r"(t), "r"((uint32_t)(n)))
#define TCGEN05_COMMIT(mb) \
    asm volatile("tcgen05.commit.cta_group::1.mbarrier::arrive::one.shared::cluster.b64 [%0];" \
        :: "r"((uint32_t)(mb)) : "memory")
#define TCGEN05_WAIT_LD()  asm volatile("tcgen05.wait::ld.sync.aligned;" ::: "memory")
#define TCGEN05_FENCE_AFTER() asm volatile("tcgen05.fence::after_thread_sync;" ::: "memory")

#define TCGEN05_LD_X16(r, addr) \
    asm volatile("tcgen05.ld.sync.aligned.32x32b.x16.b32 " \
        "{%0,%1,%2,%3,%4,%5,%6,%7,%8,%9,%10,%11,%12,%13,%14,%15}, [%16];" \
        : "=r"((r)[0]),"=r"((r)[1]),"=r"((r)[2]),"=r"((r)[3]),   \
          "=r"((r)[4]),"=r"((r)[5]),"=r"((r)[6]),"=r"((r)[7]),   \
          "=r"((r)[8]),"=r"((r)[9]),"=r"((r)[10]),"=r"((r)[11]), \
          "=r"((r)[12]),"=r"((r)[13]),"=r"((r)[14]),"=r"((r)[15]) \
        : "r"(addr))

// SW128 K-major smem descriptor (layout=2, version=1, SBO=64, LBO=1)
__device__ __forceinline__ uint64_t make_desc_sw128(uint32_t addr) {
    return ((uint64_t)2 << 61) | ((uint64_t)1 << 46) | ((uint64_t)64 << 32) |
           ((uint64_t)1 << 16) | ((uint64_t)(addr >> 4) & 0x3FFF);
}

__device__ __forceinline__ void mma_tf32_ss(uint32_t d, uint64_t ad, uint64_t bd,
                                            uint32_t idesc, uint32_t en) {
    asm volatile(
        "{ .reg .pred p; setp.ne.u32 p, %4, 0;\n\t"
        "tcgen05.mma.cta_group::1.kind::tf32 [%0], %1, %2, %3, {%5,%5,%5,%5}, p; }\n"
        :: "r"(d), "l"(ad), "l"(bd), "r"(idesc), "r"(en), "r"(0u) : "memory");
}
#endif // HAS_TCGEN05

// ---------------- main kernel ----------------
__global__ __launch_bounds__(NTHREADS, 2) void conv_tc_kernel(
    const float* __restrict__ img,
    const float* __restrict__ wts,
    float* __restrict__ out)
{
#if HAS_TCGEN05
    extern __shared__ char smem[];
    const uint32_t sb = smem_u32(smem);
    const int tid = threadIdx.x, wid = tid >> 5, lane = tid & 31;
    const int bx = blockIdx.x;
    const int b = bx / 98, mb = bx - b * 98;
    const int m_base = mb * M_TILE;

    // TMEM alloc + mbar init
    if (wid == 0) { TCGEN05_ALLOC(sb + OFF_TMEM, 256); TCGEN05_RELINQ(); }
    if (tid == 0) { MBARRIER_INIT(sb + OFF_MBAR0, 1); MBARRIER_INIT(sb + OFF_MBAR1, 1); }
    __syncthreads();
    uint32_t tmem;
    asm volatile("ld.shared.b32 %0, [%1];" : "=r"(tmem) : "r"(sb + OFF_TMEM));

    // per-thread staging geometry (loop-invariant); padded plane => no masks
    const int m  = tid & 127;
    const int qg = tid >> 7;          // 0..3; this thread stages quads qg*2, qg*2+1
    const int gm = m_base + m;
    const int y  = gm / 112, x = gm - y * 112;
    const float* up = g_upad + (size_t)b * C_IN * PAD_S + (y * PAD_W + x);

    // hoisted swizzled A store offsets (2 quads per thread) + B offset (1 task)
    uint32_t swoff[2];
    #pragma unroll
    for (int i = 0; i < 2; ++i) {
        uint32_t bo = (uint32_t)(m * 128 + (qg * 2 + i) * 16);
        swoff[i] = bo ^ ((bo >> 3) & 0x70);
    }
    const int bo_o = tid >> 3, bo_q = tid & 7;
    uint32_t bsw;
    { uint32_t v = (uint32_t)(bo_o * 128 + bo_q * 16); bsw = v ^ ((v >> 3) & 0x70); }

    // ---- register prefetch buffers (8 u values + 1 pre-rounded B float4) ----
    float av[8];
    float4 bw;

    #define PREFETCH(K0) do {                                                   \
        bw = *(const float4*)(g_wtf + bo_o * K_TOT + (K0) + bo_q * 4);          \
        _Pragma("unroll")                                                       \
        for (int _i = 0; _i < 2; ++_i) {                                        \
            int4 pk = *(const int4*)(g_offt + (K0) + (qg * 2 + _i) * 4);        \
            av[_i * 4 + 0] = __ldg(up + pk.x);                                  \
            av[_i * 4 + 1] = __ldg(up + pk.y);                                  \
            av[_i * 4 + 2] = __ldg(up + pk.z);                                  \
            av[_i * 4 + 3] = __ldg(up + pk.w);                                  \
        }                                                                       \
    } while (0)

    PREFETCH(0);

    int ph0 = 0, ph1 = 0;
    for (int ch = 0; ch < NCHUNK; ++ch) {
        const int s = ch & 1;
        const uint32_t mbar = sb + (s ? OFF_MBAR1 : OFF_MBAR0);
        // wait until MMAs of chunk ch-2 (same buffer) finished reading smem
        if (ch >= 2) {
            if (s) { MBARRIER_WAIT_PARITY(mbar, ph1); ph1 ^= 1; }
            else   { MBARRIER_WAIT_PARITY(mbar, ph0); ph0 ^= 1; }
        }
        char* Abase = smem + OFF_A + s * A_SSTRIDE;
        char* Bbase = smem + OFF_B + s * B_SSTRIDE;

        // ---- store registers -> smem (u already tf32-rounded; powers rounded here) ----
        *(float4*)(Bbase + bsw) = bw;
        #pragma unroll
        for (int i = 0; i < 2; ++i) {
            float4 r1, r2, r3;
            float* p1 = &r1.x; float* p2 = &r2.x; float* p3 = &r3.x;
            #pragma unroll
            for (int j = 0; j < 4; ++j) {
                float v = av[i * 4 + j];
                float v2 = v * v;
                p1[j] = v;
                p2[j] = tf32r_(v2);
                p3[j] = tf32r_(v2 * v);
            }
            *(float4*)(Abase + 0 * A_PSTRIDE + swoff[i]) = r1;
            *(float4*)(Abase + 1 * A_PSTRIDE + swoff[i]) = r2;
            *(float4*)(Abase + 2 * A_PSTRIDE + swoff[i]) = r3;
        }
        asm volatile("fence.proxy.async.shared::cta;" ::: "memory");
        __syncthreads();

        // ---- issue MMAs for this chunk (overlaps staging of ch+1 via double buffer) ----
        if (wid == 0 && elect_one()) {
            const uint32_t ab = sb + OFF_A + s * A_SSTRIDE;
            const uint64_t ad1 = make_desc_sw128(ab);
            const uint64_t ad2 = make_desc_sw128(ab + A_PSTRIDE);
            const uint64_t ad3 = make_desc_sw128(ab + 2 * A_PSTRIDE);
            const uint64_t bd  = make_desc_sw128(sb + OFF_B + s * B_SSTRIDE);
            #pragma unroll
            for (int st = 0; st < 4; ++st) {
                uint32_t en = (ch > 0 || st > 0) ? 1u : 0u;
                mma_tf32_ss(tmem + 0,   ad1 + st * 2, bd + st * 2, IDESC_TF32, en);
                mma_tf32_ss(tmem + 64,  ad2 + st * 2, bd + st * 2, IDESC_TF32, en);
                mma_tf32_ss(tmem + 128, ad3 + st * 2, bd + st * 2, IDESC_TF32, en);
            }
            TCGEN05_COMMIT(mbar);
        }

        // ---- prefetch next chunk (overlaps the MMAs just issued) ----
        if (ch + 1 < NCHUNK) PREFETCH((ch + 1) * KC);
    }
    // drain both buffers
    MBARRIER_WAIT_PARITY(sb + OFF_MBAR0, ph0);
    MBARRIER_WAIT_PARITY(sb + OFF_MBAR1, ph1);

    // ---- fused epilogue from TMEM (16 warps: warp -> (m-subpartition, 16-col group)) ----
    TCGEN05_FENCE_AFTER();
    const int msub = wid & 3;
    const int n0   = (wid >> 2) * 16;
    const int mg = m_base + msub * 32 + lane;

    {
        uint32_t a1[16], a2[16], a3[16];
        TCGEN05_LD_X16(a1, tmem + 0   + n0);
        TCGEN05_LD_X16(a2, tmem + 64  + n0);
        TCGEN05_LD_X16(a3, tmem + 128 + n0);
        TCGEN05_WAIT_LD();
        #pragma unroll
        for (int ni = 0; ni < 16; ++ni) {
            const int o = n0 + ni;
            float res = epilogue(__ldg(g_wsum + o),
                                 __uint_as_float(a1[ni]),
                                 __uint_as_float(a2[ni]),
                                 __uint_as_float(a3[ni]));
            out[(size_t)(b * C_OUT + o) * L_TOT + mg] = res;
        }
    }

    __syncthreads();
    if (wid == 0) TCGEN05_DEALLOC(tmem, 256);
#else
    // ---------- fallback for non-sm_103a compilation passes (never runs on GB300) ----------
    const int tid = threadIdx.x;
    const int bx = blockIdx.x;
    const int b = bx / 98, mb = bx - b * 98;
    const int m_base = mb * M_TILE;
    const float* imgb = img + (size_t)b * C_IN * L_TOT;

    for (int idx = tid; idx < M_TILE * C_OUT; idx += NTHREADS) {
        int m = idx & 127, o = idx >> 7;
        int gm = m_base + m;
        int y = gm / 112, x = gm - y * 112;
        float c1 = 0.f, c2 = 0.f, c3 = 0.f;
        for (int k = 0; k < K_TOT; ++k) {
            int c = k / 9, r = k - c * 9, dy = r / 3, dx = r - dy * 3;
            int iy = y + dy - 1, ix = x + dx - 1;
            float v = 0.f;
            if ((unsigned)iy < 112u && (unsigned)ix < 112u)
                v = imgb[c * L_TOT + iy * 112 + ix];
            float w = wts[o * K_TOT + k];
            c1 += v * w; c2 += v * v * w; c3 += v * v * v * w;
        }
        out[(size_t)(b * C_OUT + o) * L_TOT + gm] = epilogue(g_wsum[o], c1, c2, c3);
    }
#endif
}

extern "C" void kernel_launch(void* const* d_in, const int* in_sizes, int n_in,
                              void* d_out, int out_size) {
    const float* img = (const float*)d_in[0];
    const float* wts = (const float*)d_in[1];
    float* out = (float*)d_out;

    int B = in_sizes[0] / (C_IN * L_TOT);   // 8

    cudaFuncSetAttribute(conv_tc_kernel, cudaFuncAttributeMaxDynamicSharedMemorySize, SMEM_TOTAL);

    wprep_kernel<<<4, 512>>>(wts);   // 64 warps: one per output channel (+ offt table)
    {
        dim3 pg((PAD_S + 511) / 512, C_IN, B);
        uprep_kernel<<<pg, 512>>>(img);
    }
    conv_tc_kernel<<<B * 98, NTHREADS, SMEM_TOTAL>>>(img, wts, out);
}